// round 1
// baseline (speedup 1.0000x reference)
#include <cuda_runtime.h>
#include <cstdint>

// EntropyCalculator: per-row histogram entropy.
//   x: [B, 64] int32, values in [0, 40)
//   out: [B, 1] float32
// H(row) = ln(64) - (1/64) * sum_v c_v * ln(c_v)   (EPS terms negligible at 1e-3 tol)

#define NT 256          // threads per block = rows per block
#define ROW_I4 16       // 64 ints = 16 int4 per row
#define TILE_STRIDE 17  // packed-byte words per row + 1 pad (odd => conflict-free row reads)
#define NWORDS 20       // 40 vocab bins packed as 2x16-bit counts per word

__global__ __launch_bounds__(NT) void entropy_hist_kernel(
    const int4* __restrict__ x, float* __restrict__ out, int B)
{
    __shared__ uint32_t tile[NT * TILE_STRIDE];   // byte-packed ids, 16 words/row
    __shared__ uint32_t hist[NWORDS * NT];        // per-thread 16-bit packed counts
    __shared__ float    lut[65];                  // lut[c] = c * ln(c)

    const int tid  = threadIdx.x;
    const int row0 = blockIdx.x * NT;

    // Build c*ln(c) LUT (once per block; 65 logf calls total)
    if (tid <= 64) {
        lut[tid] = (tid == 0) ? 0.0f : (float)tid * logf((float)tid);
    }

    // Zero histograms
    #pragma unroll
    for (int i = 0; i < NWORDS; i++) hist[i * NT + tid] = 0u;

    // Stage 256 rows (fully coalesced int4 global loads), pack ids to bytes.
    const int rows_here = min(NT, B - row0);            // full blocks in practice
    const int e_limit   = rows_here * ROW_I4;
    const int4* gp = x + (size_t)row0 * ROW_I4;
    #pragma unroll
    for (int k = 0; k < ROW_I4; k++) {
        int e = tid + k * NT;
        if (e < e_limit) {
            int4 w = __ldcs(&gp[e]);
            uint32_t p = (uint32_t)w.x | ((uint32_t)w.y << 8) |
                         ((uint32_t)w.z << 16) | ((uint32_t)w.w << 24);
            int r = e >> 4;
            int j = e & 15;
            tile[r * TILE_STRIDE + j] = p;
        }
    }
    __syncthreads();

    const int row = row0 + tid;
    if (row < B) {
        // Histogram own row from smem (conflict-free: stride 17 pitch, tid-banked hist)
        const uint32_t* my = &tile[tid * TILE_STRIDE];
        #pragma unroll
        for (int j = 0; j < ROW_I4; j++) {
            uint32_t p = my[j];
            #pragma unroll
            for (int b = 0; b < 4; b++) {
                uint32_t v   = (p >> (8 * b)) & 0xFFu;
                uint32_t idx = (v >> 1) * NT + (uint32_t)tid;
                uint32_t add = 1u << ((v & 1u) << 4);
                hist[idx] += add;   // private column: no races, bank = tid%32
            }
        }

        // Entropy: H = ln(64) - (1/64) * sum c*ln(c)
        float acc = 0.0f;
        #pragma unroll
        for (int i = 0; i < NWORDS; i++) {
            uint32_t w = hist[i * NT + tid];
            acc += lut[w & 0xFFFFu] + lut[w >> 16];
        }
        out[row] = 4.1588830833596718565f - acc * 0.015625f;  // ln(64) - acc/64
    }
}

extern "C" void kernel_launch(void* const* d_in, const int* in_sizes, int n_in,
                              void* d_out, int out_size)
{
    const int4* x = (const int4*)d_in[0];
    float* out    = (float*)d_out;
    int B = in_sizes[0] / 64;
    int grid = (B + NT - 1) / NT;
    entropy_hist_kernel<<<grid, NT>>>(x, out, B);
}